// round 9
// baseline (speedup 1.0000x reference)
#include <cuda_runtime.h>
#include <cuda_fp16.h>
#include <cstdint>

// ---------------- problem constants ----------------
namespace cfg {
constexpr int   N    = 100000;
constexpr int   D    = 128;
constexpr int   P    = 64;
constexpr int   E    = 3200000;
constexpr int   EPT  = 5000000;
constexpr float INV_EPS = 10.0f;           // 1/0.1
constexpr int   ITERS   = 20;
constexpr float A_MARG  = 1.0f / 100000.0f;
constexpr float B_MARG  = 1.0f / 64.0f;
}

// ---------------- device scratch (static, no allocs) ----------------
__device__ int   g_cnt[cfg::N];                      // row histogram (CSR)
__device__ int   g_degc[cfg::N];                     // col histogram (GCN deg)
__device__ float g_dis[cfg::N];                      // deg^-1/2
__device__ int   g_off[cfg::N];                      // CSR segment base
__device__ int   g_cursor[cfg::N];                   // CSR fill cursor
__device__ int2  g_epay[cfg::E];                     // CSR payload: (col, ew-bits)
__device__ int   g_total;                            // segment allocator
__device__ __half g_xd[(size_t)cfg::N * cfg::D];     // fp16 dis[c]*x[c] (gathers)
__device__ float g_aggr[(size_t)cfg::N * cfg::D];    // aggregation result
__device__ __half g_xfh[(size_t)cfg::N * cfg::D];    // normalized x_adapted (fp16)
__device__ unsigned g_Kh[(size_t)(cfg::P / 2) * cfg::N]; // half2 K: [k][n], p=(2k,2k+1)
__device__ unsigned g_Sh[(size_t)(cfg::P / 2) * cfg::N]; // half2 cos sim s, same layout
__device__ float g_u[cfg::N];
__device__ float g_KtuI[cfg::ITERS + 1][cfg::P];     // per-iteration K^T u buffers
__device__ float g_v[cfg::P];
__device__ float g_pn[cfg::P * cfg::D];              // normalized prompts
__device__ float g_loss;
__device__ unsigned int g_wmax;

// ---------------- helpers ----------------
__device__ __forceinline__ float warpAllReduceSum(float v) {
#pragma unroll
    for (int o = 16; o; o >>= 1) v += __shfl_xor_sync(0xffffffffu, v, o);
    return v;
}

// ---------------- kernels ----------------

// fused: zero scratch + normalize prompt tokens (block 0)
__global__ void k_init(const float* __restrict__ pt) {
    size_t idx    = (size_t)blockIdx.x * blockDim.x + threadIdx.x;
    size_t stride = (size_t)gridDim.x * blockDim.x;
    for (size_t i = idx; i < (size_t)cfg::N; i += stride) { g_cnt[i] = 0; g_degc[i] = 0; }
    if (idx < (size_t)((cfg::ITERS + 1) * cfg::P))
        g_KtuI[idx / cfg::P][idx % cfg::P] = 0.0f;
    if (idx == 0) { g_loss = 0.0f; g_wmax = 0u; g_total = 0; }
    if (blockIdx.x == 0) {
        int lane = threadIdx.x & 31;
        int w    = threadIdx.x >> 5;
        for (int p = w; p < cfg::P; p += 8) {
            float4 v = reinterpret_cast<const float4*>(pt + (size_t)p * cfg::D)[lane];
            float ss = warpAllReduceSum(v.x * v.x + v.y * v.y + v.z * v.z + v.w * v.w);
            float inv = 1.0f / fmaxf(sqrtf(ss), 1e-12f);
            float4 o = make_float4(v.x * inv, v.y * inv, v.z * inv, v.w * inv);
            reinterpret_cast<float4*>(g_pn + (size_t)p * cfg::D)[lane] = o;
        }
    }
}

// histograms: row buckets (CSR) and col degree (GCN norm)
__global__ void k_count(const int* __restrict__ row, const int* __restrict__ col) {
    int i = blockIdx.x * blockDim.x + threadIdx.x;
    if (i < cfg::E) {
        atomicAdd(&g_cnt[row[i]], 1);
        atomicAdd(&g_degc[col[i]], 1);
    }
}

// per node: deg^-1/2 and CSR segment allocation (ticket; order irrelevant)
__global__ void k_node() {
    int i = blockIdx.x * blockDim.x + threadIdx.x;
    if (i < cfg::N) {
        int d = g_degc[i];
        g_dis[i] = (d > 0) ? rsqrtf((float)d) : 0.0f;
        int c = g_cnt[i];
        int base = atomicAdd(&g_total, c);
        g_off[i] = base;
        g_cursor[i] = base;
    }
}

// fp16 dis-prescaled copy of x: xd[n][d] = dis[n] * x[n][d]
__global__ void k_xd(const float* __restrict__ x) {
    size_t idx    = (size_t)blockIdx.x * blockDim.x + threadIdx.x;
    size_t stride = (size_t)gridDim.x * blockDim.x;
    const float4* x4 = reinterpret_cast<const float4*>(x);
    uint2* xd2 = reinterpret_cast<uint2*>(g_xd);
    size_t total = (size_t)cfg::N * cfg::D / 4;
    for (size_t i = idx; i < total; i += stride) {
        float dn = g_dis[i >> 5];      // 32 consecutive float4 per node
        float4 v = x4[i];
        __half2 h0 = __floats2half2_rn(v.x * dn, v.y * dn);
        __half2 h1 = __floats2half2_rn(v.z * dn, v.w * dn);
        uint2 pk;
        pk.x = *reinterpret_cast<unsigned*>(&h0);
        pk.y = *reinterpret_cast<unsigned*>(&h1);
        xd2[i] = pk;
    }
}

// per edge: drop (col, ew) payload into row's CSR segment (no dis fetches)
__global__ void k_fill(const int* __restrict__ row, const int* __restrict__ col,
                       const float* __restrict__ ew) {
    int i = blockIdx.x * blockDim.x + threadIdx.x;
    if (i < cfg::E) {
        int r = row[i];
        int pos = atomicAdd(&g_cursor[r], 1);
        g_epay[pos] = make_int2(col[i], __float_as_int(ew[i]));
    }
}

// warp per node: aggr = dis[n] * sum(ew * xd[col]) over node's CSR segment
__global__ void k_aggr() {
    int lane = threadIdx.x & 31;
    int n    = (blockIdx.x * blockDim.x + threadIdx.x) >> 5;
    if (n >= cfg::N) return;
    int base = g_off[n];
    int cnt  = g_cnt[n];
    const uint2* xd2 = reinterpret_cast<const uint2*>(g_xd);
    float4 a0 = make_float4(0.f, 0.f, 0.f, 0.f);
    float4 a1 = make_float4(0.f, 0.f, 0.f, 0.f);
    int j = 0;
    for (; j + 4 <= cnt; j += 4) {
        int2 p0 = g_epay[base + j];
        int2 p1 = g_epay[base + j + 1];
        int2 p2 = g_epay[base + j + 2];
        int2 p3 = g_epay[base + j + 3];
        uint2 r0 = __ldg(&xd2[(size_t)p0.x * 32 + lane]);
        uint2 r1 = __ldg(&xd2[(size_t)p1.x * 32 + lane]);
        uint2 r2 = __ldg(&xd2[(size_t)p2.x * 32 + lane]);
        uint2 r3 = __ldg(&xd2[(size_t)p3.x * 32 + lane]);
        float w0 = __int_as_float(p0.y), w1 = __int_as_float(p1.y);
        float w2 = __int_as_float(p2.y), w3 = __int_as_float(p3.y);
        float2 f;
        f = __half22float2(*reinterpret_cast<__half2*>(&r0.x)); a0.x += w0*f.x; a0.y += w0*f.y;
        f = __half22float2(*reinterpret_cast<__half2*>(&r0.y)); a0.z += w0*f.x; a0.w += w0*f.y;
        f = __half22float2(*reinterpret_cast<__half2*>(&r1.x)); a1.x += w1*f.x; a1.y += w1*f.y;
        f = __half22float2(*reinterpret_cast<__half2*>(&r1.y)); a1.z += w1*f.x; a1.w += w1*f.y;
        f = __half22float2(*reinterpret_cast<__half2*>(&r2.x)); a0.x += w2*f.x; a0.y += w2*f.y;
        f = __half22float2(*reinterpret_cast<__half2*>(&r2.y)); a0.z += w2*f.x; a0.w += w2*f.y;
        f = __half22float2(*reinterpret_cast<__half2*>(&r3.x)); a1.x += w3*f.x; a1.y += w3*f.y;
        f = __half22float2(*reinterpret_cast<__half2*>(&r3.y)); a1.z += w3*f.x; a1.w += w3*f.y;
    }
    for (; j < cnt; ++j) {
        int2 p0 = g_epay[base + j];
        uint2 r0 = __ldg(&xd2[(size_t)p0.x * 32 + lane]);
        float w0 = __int_as_float(p0.y);
        float2 f;
        f = __half22float2(*reinterpret_cast<__half2*>(&r0.x)); a0.x += w0*f.x; a0.y += w0*f.y;
        f = __half22float2(*reinterpret_cast<__half2*>(&r0.y)); a0.z += w0*f.x; a0.w += w0*f.y;
    }
    float dn = g_dis[n];
    float4 acc = make_float4(dn * (a0.x + a1.x), dn * (a0.y + a1.y),
                             dn * (a0.z + a1.z), dn * (a0.w + a1.w));
    reinterpret_cast<float4*>(g_aggr)[(size_t)n * 32 + lane] = acc;
}

// Fused: per block of 128 nodes, build normalized xs in swizzled smem, then
// register-tiled GEMM against pn -> packed half2 K [32][N] + half2 s; fused Ktu0.
__global__ void k_ck(const float* __restrict__ x, const float* __restrict__ gammap) {
    extern __shared__ float sm[];
    float* xs_s = sm;            // 128*128
    float* pn_s = sm + 16384;    // 128*64
    int t  = threadIdx.x;
    int nb = blockIdx.x * 128;
    float gm = *gammap;

    for (int idx = t; idx < cfg::P * cfg::D; idx += 256) {
        int p = idx >> 7, d = idx & 127;
        pn_s[d * 64 + p] = g_pn[idx];
    }

    int lane = t & 31, w = t >> 5;
    for (int it = 0; it < 16; ++it) {
        int nl = w + 8 * it;
        int n  = nb + nl;
        bool act = (n < cfg::N);
        float xs[4];
        float ss = 0.0f;
#pragma unroll
        for (int m = 0; m < 4; ++m) {
            int d = lane + 32 * m;
            float xv = act ? x[(size_t)n * 128 + d] : 0.0f;
            float ag = act ? g_aggr[(size_t)n * 128 + d] : 0.0f;
            xs[m] = (1.0f - gm) * xv + gm * ag;
            ss += xs[m] * xs[m];
        }
        ss = warpAllReduceSum(ss);
        float inv = 1.0f / fmaxf(sqrtf(ss), 1e-12f);
#pragma unroll
        for (int m = 0; m < 4; ++m) {
            int d = lane + 32 * m;
            xs_s[d * 128 + ((nl + d) & 127)] = xs[m] * inv;
        }
    }
    __syncthreads();

    int tx = t & 31, ty = t >> 5;
    float acc[4][8];
#pragma unroll
    for (int i = 0; i < 4; ++i)
#pragma unroll
        for (int j = 0; j < 8; ++j) acc[i][j] = 0.0f;

#pragma unroll 4
    for (int k = 0; k < 128; ++k) {
        float a[4];
#pragma unroll
        for (int i = 0; i < 4; ++i)
            a[i] = xs_s[k * 128 + ((tx + 32 * i + k) & 127)];
        float b[8];
#pragma unroll
        for (int j = 0; j < 8; ++j)
            b[j] = pn_s[k * 64 + ty * 8 + j];
#pragma unroll
        for (int i = 0; i < 4; ++i)
#pragma unroll
            for (int j = 0; j < 8; ++j)
                acc[i][j] += a[i] * b[j];
    }

    // epilogue: K = exp((s-1)*10) -> half2 [32][N]; s -> half2; accumulate Ktu0
    float ksum[8];
#pragma unroll
    for (int j = 0; j < 8; ++j) ksum[j] = 0.0f;
#pragma unroll
    for (int i = 0; i < 4; ++i) {
        int n = nb + tx + 32 * i;
        bool act = (n < cfg::N);
        float kv[8];
#pragma unroll
        for (int j = 0; j < 8; ++j) {
            kv[j] = __expf((acc[i][j] - 1.0f) * cfg::INV_EPS);
            if (act) ksum[j] += kv[j];
        }
        if (act) {
#pragma unroll
            for (int m = 0; m < 4; ++m) {
                __half2 h = __floats2half2_rn(kv[2 * m], kv[2 * m + 1]);
                g_Kh[(size_t)(ty * 4 + m) * cfg::N + n] = *reinterpret_cast<unsigned*>(&h);
                __half2 hs = __floats2half2_rn(acc[i][2 * m], acc[i][2 * m + 1]);
                g_Sh[(size_t)(ty * 4 + m) * cfg::N + n] = *reinterpret_cast<unsigned*>(&hs);
            }
        }
    }
#pragma unroll
    for (int j = 0; j < 8; ++j) {
        float tot = warpAllReduceSum(ksum[j]);
        if (tx == 0) atomicAdd(&g_KtuI[0][ty * 8 + j], cfg::A_MARG * tot);
    }
}

// One Sinkhorn pass per launch, j=1..20: v = b/Ktu[j-1]; u = a/(K v);
// j<20: Ktu[j] = K^T u. j=20: store u (and v).
__global__ void k_ua(int j) {
    __shared__ float sv[cfg::P];
    __shared__ float sKtu[cfg::P];
    int t = threadIdx.x;
    if (t < cfg::P) {
        sKtu[t] = 0.0f;
        float v = cfg::B_MARG / (g_KtuI[j - 1][t] + 1e-30f);
        sv[t] = v;
        if (j == cfg::ITERS && blockIdx.x == 0) g_v[t] = v;
    }
    __syncthreads();

    int n = blockIdx.x * 256 + t;
    bool act = (n < cfg::N);
    int nn = act ? n : 0;

    float kreg[64];
#pragma unroll
    for (int k = 0; k < 32; ++k) {
        unsigned raw = g_Kh[(size_t)k * cfg::N + nn];
        float2 f = __half22float2(*reinterpret_cast<__half2*>(&raw));
        kreg[2 * k]     = f.x;
        kreg[2 * k + 1] = f.y;
    }

    float kv = 0.0f;
#pragma unroll
    for (int p = 0; p < 64; ++p) kv += kreg[p] * sv[p];
    float u = cfg::A_MARG / (kv + 1e-30f);

    if (j == cfg::ITERS) {
        if (act) g_u[n] = u;
        return;
    }
    float ua = act ? u : 0.0f;
#pragma unroll
    for (int p = 0; p < 64; ++p) kreg[p] *= ua;

    int lane = t & 31;
#pragma unroll
    for (int k = 0; k < 5; ++k) {
        int off = 16 >> k;
        int c   = 32 >> k;
        bool up = (lane & off) != 0;
#pragma unroll
        for (int i = 0; i < 32; ++i) {
            if (i < c) {
                float mine  = up ? kreg[i + c] : kreg[i];
                float other = up ? kreg[i]     : kreg[i + c];
                kreg[i] = mine + __shfl_xor_sync(0xffffffffu, other, off);
            }
        }
    }
    atomicAdd(&sKtu[2 * lane],     kreg[0]);
    atomicAdd(&sKtu[2 * lane + 1], kreg[1]);
    __syncthreads();
    if (t < cfg::P) atomicAdd(&g_KtuI[j][t], sKtu[t]);
}

// warp per node: prompt message, ot_loss, x_adapted -> out, xf(half) = l2norm.
// Reads half2 K and half2 s; lossn uses c = 1 - s (no MUFU logs).
__global__ void k_final(const float* __restrict__ x, const float* __restrict__ pt,
                        const float* __restrict__ alphap, float* __restrict__ out) {
    __shared__ float spt[cfg::P * cfg::D];
    __shared__ float sv[cfg::P];
    __shared__ float sLoss;
    for (int i = threadIdx.x; i < cfg::P * cfg::D; i += blockDim.x) spt[i] = pt[i];
    if (threadIdx.x < cfg::P) sv[threadIdx.x] = g_v[threadIdx.x];
    if (threadIdx.x == 0) sLoss = 0.0f;
    __syncthreads();
    float coef = (*alphap) * (float)cfg::N;
    int lane   = threadIdx.x & 31;
    int warpId = (blockIdx.x * blockDim.x + threadIdx.x) >> 5;
    int nWarps = (gridDim.x * blockDim.x) >> 5;
    const float4* spt4 = reinterpret_cast<const float4*>(spt);
    float lacc = 0.0f;
    for (int n = warpId; n < cfg::N; n += nWarps) {
        float u = g_u[n];
        float4 m = make_float4(0.f, 0.f, 0.f, 0.f);
        float lossn = 0.0f;
#pragma unroll 4
        for (int k = 0; k < 32; ++k) {
            unsigned raw = g_Kh[(size_t)k * cfg::N + n];   // warp broadcast
            unsigned raws = g_Sh[(size_t)k * cfg::N + n];  // warp broadcast
            float2 f = __half22float2(*reinterpret_cast<__half2*>(&raw));
            float2 s = __half22float2(*reinterpret_cast<__half2*>(&raws));
            float kv0 = f.x * sv[2 * k];
            float kv1 = f.y * sv[2 * k + 1];
            float4 p0 = spt4[(2 * k) * 32 + lane];
            float4 p1 = spt4[(2 * k + 1) * 32 + lane];
            m.x += kv0 * p0.x + kv1 * p1.x;
            m.y += kv0 * p0.y + kv1 * p1.y;
            m.z += kv0 * p0.z + kv1 * p1.z;
            m.w += kv0 * p0.w + kv1 * p1.w;
            lossn += kv0 * (1.0f - s.x) + kv1 * (1.0f - s.y);
        }
        lacc += u * lossn;
        float4 xv = reinterpret_cast<const float4*>(x + (size_t)n * cfg::D)[lane];
        float cu = coef * u;
        float4 xa = make_float4(xv.x + cu * m.x, xv.y + cu * m.y,
                                xv.z + cu * m.z, xv.w + cu * m.w);
        reinterpret_cast<float4*>(out + (size_t)n * cfg::D)[lane] = xa;
        float ss = warpAllReduceSum(xa.x * xa.x + xa.y * xa.y + xa.z * xa.z + xa.w * xa.w);
        float inv = 1.0f / fmaxf(sqrtf(ss), 1e-12f);
        __half2 h01 = __floats2half2_rn(xa.x * inv, xa.y * inv);
        __half2 h23 = __floats2half2_rn(xa.z * inv, xa.w * inv);
        uint2 pk;
        pk.x = *reinterpret_cast<unsigned*>(&h01);
        pk.y = *reinterpret_cast<unsigned*>(&h23);
        reinterpret_cast<uint2*>(g_xfh)[(size_t)n * 32 + lane] = pk;
    }
    if (lane == 0) atomicAdd(&sLoss, lacc);
    __syncthreads();
    if (threadIdx.x == 0) atomicAdd(&g_loss, sLoss);
}

__device__ __forceinline__ float dot8h(uint4 a, uint4 b) {
    const unsigned* pa = &a.x;
    const unsigned* pb = &b.x;
    float s = 0.0f;
#pragma unroll
    for (int i = 0; i < 4; ++i) {
        float2 fa = __half22float2(*reinterpret_cast<const __half2*>(pa + i));
        float2 fb = __half22float2(*reinterpret_cast<const __half2*>(pb + i));
        s += fa.x * fb.x + fa.y * fb.y;
    }
    return s;
}

// half-warp (16 lanes) per prompt-edge on fp16 xf: w = relu(dot); track max
__global__ void k_edge(const int* __restrict__ prow, const int* __restrict__ pcol,
                       float* __restrict__ outw) {
    __shared__ unsigned int smax;
    if (threadIdx.x == 0) smax = 0u;
    __syncthreads();
    int t    = threadIdx.x;
    int lane = t & 31;
    int sub  = lane >> 4;
    int sl   = lane & 15;
    int wid  = (blockIdx.x * blockDim.x + t) >> 5;
    int nW   = (gridDim.x * blockDim.x) >> 5;
    const uint4* xf4 = reinterpret_cast<const uint4*>(g_xfh);
    float lmax = 0.0f;
    for (int e0 = wid * 2; e0 < cfg::EPT; e0 += nW * 2) {
        int e = e0 + sub;
        float ts = 0.0f;
        bool act = (e < cfg::EPT);
        if (act) {
            int r = prow[e], c = pcol[e];
            uint4 av = __ldg(&xf4[(size_t)r * 16 + sl]);
            uint4 bv = __ldg(&xf4[(size_t)c * 16 + sl]);
            ts = dot8h(av, bv);
        }
#pragma unroll
        for (int o = 8; o; o >>= 1) ts += __shfl_xor_sync(0xffffffffu, ts, o);
        if (sl == 0 && act) {
            float wv = fmaxf(ts, 0.0f);
            outw[e] = wv;
            lmax = fmaxf(lmax, wv);
        }
    }
    atomicMax(&smax, __float_as_uint(lmax));
    __syncthreads();
    if (threadIdx.x == 0) atomicMax(&g_wmax, smax);
}

// scale w in place; emit ot_loss
__global__ void k_scale(float* __restrict__ out) {
    float inv = 1.0f / (__uint_as_float(g_wmax) + 1e-8f);
    float* w = out + (size_t)cfg::N * cfg::D + 1;
    size_t idx    = (size_t)blockIdx.x * blockDim.x + threadIdx.x;
    size_t stride = (size_t)gridDim.x * blockDim.x;
    for (size_t e = idx; e < (size_t)cfg::EPT; e += stride) w[e] *= inv;
    if (blockIdx.x == 0 && threadIdx.x == 0) out[(size_t)cfg::N * cfg::D] = g_loss;
}

// ---------------- launch ----------------
extern "C" void kernel_launch(void* const* d_in, const int* in_sizes, int n_in,
                              void* d_out, int out_size) {
    const float* x     = (const float*)d_in[0];
    const int*   ei    = (const int*)d_in[1];
    const float* ew    = (const float*)d_in[2];
    const int*   pei   = (const int*)d_in[3];
    const float* pt    = (const float*)d_in[4];
    const float* alpha = (const float*)d_in[5];
    const float* gamma = (const float*)d_in[6];
    float* out = (float*)d_out;

    const int* row  = ei;
    const int* col  = ei + cfg::E;
    const int* prow = pei;
    const int* pcol = pei + cfg::EPT;

    cudaFuncSetAttribute(k_ck, cudaFuncAttributeMaxDynamicSharedMemorySize, 98304);

    k_init<<<512, 256>>>(pt);
    k_count<<<(cfg::E + 255) / 256, 256>>>(row, col);
    k_node<<<(cfg::N + 255) / 256, 256>>>();
    k_xd<<<2048, 256>>>(x);
    k_fill<<<(cfg::E + 255) / 256, 256>>>(row, col, ew);
    k_aggr<<<(cfg::N * 32 + 255) / 256, 256>>>();
    k_ck<<<(cfg::N + 127) / 128, 256, 98304>>>(x, gamma);   // includes Ktu0

    for (int j = 1; j <= cfg::ITERS; ++j)
        k_ua<<<(cfg::N + 255) / 256, 256>>>(j);

    k_final<<<2048, 256>>>(x, pt, alpha, out);
    k_edge<<<8192, 256>>>(prow, pcol, out + (size_t)cfg::N * cfg::D + 1);
    k_scale<<<4096, 256>>>(out);
}

// round 10
// speedup vs baseline: 1.0215x; 1.0215x over previous
#include <cuda_runtime.h>
#include <cuda_fp16.h>
#include <cstdint>

// ---------------- problem constants ----------------
namespace cfg {
constexpr int   N    = 100000;
constexpr int   D    = 128;
constexpr int   P    = 64;
constexpr int   E    = 3200000;
constexpr int   EPT  = 5000000;
constexpr float INV_EPS = 10.0f;           // 1/0.1
constexpr int   ITERS   = 20;
constexpr float A_MARG  = 1.0f / 100000.0f;
constexpr float B_MARG  = 1.0f / 64.0f;
}

// ---------------- device scratch (static, no allocs) ----------------
__device__ int   g_cnt[cfg::N];                      // row histogram (CSR)
__device__ int   g_degc[cfg::N];                     // col histogram (GCN deg)
__device__ float g_dis[cfg::N];                      // deg^-1/2
__device__ int   g_off[cfg::N];                      // CSR segment base
__device__ int   g_cursor[cfg::N];                   // CSR fill cursor
__device__ int2  g_epay[cfg::E];                     // CSR payload: (col, ew-bits)
__device__ int   g_total;                            // segment allocator
__device__ __half g_xd[(size_t)cfg::N * cfg::D];     // fp16 dis[c]*x[c] (gathers)
__device__ float g_aggr[(size_t)cfg::N * cfg::D];    // aggregation result
__device__ __half g_xfh[(size_t)cfg::N * cfg::D];    // normalized x_adapted (fp16)
__device__ unsigned g_Kh[(size_t)(cfg::P / 2) * cfg::N]; // half2 K: [k][n], p=(2k,2k+1)
__device__ float g_u[cfg::N];
__device__ float g_KtuI[cfg::ITERS + 1][cfg::P];     // per-iteration K^T u buffers
__device__ float g_v[cfg::P];
__device__ float g_pn[cfg::P * cfg::D];              // normalized prompts
__device__ float g_loss;
__device__ unsigned int g_wmax;

// ---------------- helpers ----------------
__device__ __forceinline__ float warpAllReduceSum(float v) {
#pragma unroll
    for (int o = 16; o; o >>= 1) v += __shfl_xor_sync(0xffffffffu, v, o);
    return v;
}

// ---------------- kernels ----------------

// fused: zero scratch + normalize prompt tokens (block 0)
__global__ void k_init(const float* __restrict__ pt) {
    size_t idx    = (size_t)blockIdx.x * blockDim.x + threadIdx.x;
    size_t stride = (size_t)gridDim.x * blockDim.x;
    for (size_t i = idx; i < (size_t)cfg::N; i += stride) { g_cnt[i] = 0; g_degc[i] = 0; }
    if (idx < (size_t)((cfg::ITERS + 1) * cfg::P))
        g_KtuI[idx / cfg::P][idx % cfg::P] = 0.0f;
    if (idx == 0) { g_loss = 0.0f; g_wmax = 0u; g_total = 0; }
    if (blockIdx.x == 0) {
        int lane = threadIdx.x & 31;
        int w    = threadIdx.x >> 5;
        for (int p = w; p < cfg::P; p += 8) {
            float4 v = reinterpret_cast<const float4*>(pt + (size_t)p * cfg::D)[lane];
            float ss = warpAllReduceSum(v.x * v.x + v.y * v.y + v.z * v.z + v.w * v.w);
            float inv = 1.0f / fmaxf(sqrtf(ss), 1e-12f);
            float4 o = make_float4(v.x * inv, v.y * inv, v.z * inv, v.w * inv);
            reinterpret_cast<float4*>(g_pn + (size_t)p * cfg::D)[lane] = o;
        }
    }
}

// histograms: row buckets (CSR) and col degree (GCN norm)
__global__ void k_count(const int* __restrict__ row, const int* __restrict__ col) {
    int i = blockIdx.x * blockDim.x + threadIdx.x;
    if (i < cfg::E) {
        atomicAdd(&g_cnt[row[i]], 1);
        atomicAdd(&g_degc[col[i]], 1);
    }
}

// warp per node: lane0 computes deg^-1/2 + CSR ticket; all lanes write fp16 xd = dis*x
__global__ void k_node_xd(const float* __restrict__ x) {
    int lane = threadIdx.x & 31;
    int n    = (blockIdx.x * blockDim.x + threadIdx.x) >> 5;
    if (n >= cfg::N) return;
    float dn = 0.0f;
    if (lane == 0) {
        int d = g_degc[n];
        dn = (d > 0) ? rsqrtf((float)d) : 0.0f;
        g_dis[n] = dn;
        int c = g_cnt[n];
        int base = atomicAdd(&g_total, c);
        g_off[n] = base;
        g_cursor[n] = base;
    }
    dn = __shfl_sync(0xffffffffu, dn, 0);
    float4 v = reinterpret_cast<const float4*>(x)[(size_t)n * 32 + lane];
    __half2 h0 = __floats2half2_rn(v.x * dn, v.y * dn);
    __half2 h1 = __floats2half2_rn(v.z * dn, v.w * dn);
    uint2 pk;
    pk.x = *reinterpret_cast<unsigned*>(&h0);
    pk.y = *reinterpret_cast<unsigned*>(&h1);
    reinterpret_cast<uint2*>(g_xd)[(size_t)n * 32 + lane] = pk;
}

// per edge: drop (col, ew) payload into row's CSR segment (no dis fetches)
__global__ void k_fill(const int* __restrict__ row, const int* __restrict__ col,
                       const float* __restrict__ ew) {
    int i = blockIdx.x * blockDim.x + threadIdx.x;
    if (i < cfg::E) {
        int r = row[i];
        int pos = atomicAdd(&g_cursor[r], 1);
        g_epay[pos] = make_int2(col[i], __float_as_int(ew[i]));
    }
}

// warp per node: aggr = dis[n] * sum(ew * xd[col]) over node's CSR segment
__global__ void k_aggr() {
    int lane = threadIdx.x & 31;
    int n    = (blockIdx.x * blockDim.x + threadIdx.x) >> 5;
    if (n >= cfg::N) return;
    int base = g_off[n];
    int cnt  = g_cnt[n];
    const uint2* xd2 = reinterpret_cast<const uint2*>(g_xd);
    float4 a0 = make_float4(0.f, 0.f, 0.f, 0.f);
    float4 a1 = make_float4(0.f, 0.f, 0.f, 0.f);
    int j = 0;
    for (; j + 4 <= cnt; j += 4) {
        int2 p0 = g_epay[base + j];
        int2 p1 = g_epay[base + j + 1];
        int2 p2 = g_epay[base + j + 2];
        int2 p3 = g_epay[base + j + 3];
        uint2 r0 = __ldg(&xd2[(size_t)p0.x * 32 + lane]);
        uint2 r1 = __ldg(&xd2[(size_t)p1.x * 32 + lane]);
        uint2 r2 = __ldg(&xd2[(size_t)p2.x * 32 + lane]);
        uint2 r3 = __ldg(&xd2[(size_t)p3.x * 32 + lane]);
        float w0 = __int_as_float(p0.y), w1 = __int_as_float(p1.y);
        float w2 = __int_as_float(p2.y), w3 = __int_as_float(p3.y);
        float2 f;
        f = __half22float2(*reinterpret_cast<__half2*>(&r0.x)); a0.x += w0*f.x; a0.y += w0*f.y;
        f = __half22float2(*reinterpret_cast<__half2*>(&r0.y)); a0.z += w0*f.x; a0.w += w0*f.y;
        f = __half22float2(*reinterpret_cast<__half2*>(&r1.x)); a1.x += w1*f.x; a1.y += w1*f.y;
        f = __half22float2(*reinterpret_cast<__half2*>(&r1.y)); a1.z += w1*f.x; a1.w += w1*f.y;
        f = __half22float2(*reinterpret_cast<__half2*>(&r2.x)); a0.x += w2*f.x; a0.y += w2*f.y;
        f = __half22float2(*reinterpret_cast<__half2*>(&r2.y)); a0.z += w2*f.x; a0.w += w2*f.y;
        f = __half22float2(*reinterpret_cast<__half2*>(&r3.x)); a1.x += w3*f.x; a1.y += w3*f.y;
        f = __half22float2(*reinterpret_cast<__half2*>(&r3.y)); a1.z += w3*f.x; a1.w += w3*f.y;
    }
    for (; j < cnt; ++j) {
        int2 p0 = g_epay[base + j];
        uint2 r0 = __ldg(&xd2[(size_t)p0.x * 32 + lane]);
        float w0 = __int_as_float(p0.y);
        float2 f;
        f = __half22float2(*reinterpret_cast<__half2*>(&r0.x)); a0.x += w0*f.x; a0.y += w0*f.y;
        f = __half22float2(*reinterpret_cast<__half2*>(&r0.y)); a0.z += w0*f.x; a0.w += w0*f.y;
    }
    float dn = g_dis[n];
    float4 acc = make_float4(dn * (a0.x + a1.x), dn * (a0.y + a1.y),
                             dn * (a0.z + a1.z), dn * (a0.w + a1.w));
    reinterpret_cast<float4*>(g_aggr)[(size_t)n * 32 + lane] = acc;
}

// Fused: per block of 128 nodes, build normalized xs in swizzled smem, then
// register-tiled GEMM against pn -> packed half2 K [32][N]; fused Ktu0.
__global__ void k_ck(const float* __restrict__ x, const float* __restrict__ gammap) {
    extern __shared__ float sm[];
    float* xs_s = sm;            // 128*128
    float* pn_s = sm + 16384;    // 128*64
    int t  = threadIdx.x;
    int nb = blockIdx.x * 128;
    float gm = *gammap;

    for (int idx = t; idx < cfg::P * cfg::D; idx += 256) {
        int p = idx >> 7, d = idx & 127;
        pn_s[d * 64 + p] = g_pn[idx];
    }

    int lane = t & 31, w = t >> 5;
    for (int it = 0; it < 16; ++it) {
        int nl = w + 8 * it;
        int n  = nb + nl;
        bool act = (n < cfg::N);
        float xs[4];
        float ss = 0.0f;
#pragma unroll
        for (int m = 0; m < 4; ++m) {
            int d = lane + 32 * m;
            float xv = act ? x[(size_t)n * 128 + d] : 0.0f;
            float ag = act ? g_aggr[(size_t)n * 128 + d] : 0.0f;
            xs[m] = (1.0f - gm) * xv + gm * ag;
            ss += xs[m] * xs[m];
        }
        ss = warpAllReduceSum(ss);
        float inv = 1.0f / fmaxf(sqrtf(ss), 1e-12f);
#pragma unroll
        for (int m = 0; m < 4; ++m) {
            int d = lane + 32 * m;
            xs_s[d * 128 + ((nl + d) & 127)] = xs[m] * inv;
        }
    }
    __syncthreads();

    int tx = t & 31, ty = t >> 5;
    float acc[4][8];
#pragma unroll
    for (int i = 0; i < 4; ++i)
#pragma unroll
        for (int j = 0; j < 8; ++j) acc[i][j] = 0.0f;

#pragma unroll 4
    for (int k = 0; k < 128; ++k) {
        float a[4];
#pragma unroll
        for (int i = 0; i < 4; ++i)
            a[i] = xs_s[k * 128 + ((tx + 32 * i + k) & 127)];
        float b[8];
#pragma unroll
        for (int j = 0; j < 8; ++j)
            b[j] = pn_s[k * 64 + ty * 8 + j];
#pragma unroll
        for (int i = 0; i < 4; ++i)
#pragma unroll
            for (int j = 0; j < 8; ++j)
                acc[i][j] += a[i] * b[j];
    }

    // epilogue: K = exp((s-1)*10) -> half2 [32][N]; accumulate Ktu0
    float ksum[8];
#pragma unroll
    for (int j = 0; j < 8; ++j) ksum[j] = 0.0f;
#pragma unroll
    for (int i = 0; i < 4; ++i) {
        int n = nb + tx + 32 * i;
        bool act = (n < cfg::N);
        float kv[8];
#pragma unroll
        for (int j = 0; j < 8; ++j) {
            kv[j] = __expf((acc[i][j] - 1.0f) * cfg::INV_EPS);
            if (act) ksum[j] += kv[j];
        }
        if (act) {
#pragma unroll
            for (int m = 0; m < 4; ++m) {
                __half2 h = __floats2half2_rn(kv[2 * m], kv[2 * m + 1]);
                g_Kh[(size_t)(ty * 4 + m) * cfg::N + n] = *reinterpret_cast<unsigned*>(&h);
            }
        }
    }
#pragma unroll
    for (int j = 0; j < 8; ++j) {
        float tot = warpAllReduceSum(ksum[j]);
        if (tx == 0) atomicAdd(&g_KtuI[0][ty * 8 + j], cfg::A_MARG * tot);
    }
}

// One Sinkhorn pass per launch, j=1..20: v = b/Ktu[j-1]; u = a/(K v);
// j<20: Ktu[j] = K^T u. j=20: store u (and v).
__global__ void k_ua(int j) {
    __shared__ float sv[cfg::P];
    __shared__ float sKtu[cfg::P];
    int t = threadIdx.x;
    if (t < cfg::P) {
        sKtu[t] = 0.0f;
        float v = cfg::B_MARG / (g_KtuI[j - 1][t] + 1e-30f);
        sv[t] = v;
        if (j == cfg::ITERS && blockIdx.x == 0) g_v[t] = v;
    }
    __syncthreads();

    int n = blockIdx.x * 256 + t;
    bool act = (n < cfg::N);
    int nn = act ? n : 0;

    float kreg[64];
#pragma unroll
    for (int k = 0; k < 32; ++k) {
        unsigned raw = g_Kh[(size_t)k * cfg::N + nn];
        float2 f = __half22float2(*reinterpret_cast<__half2*>(&raw));
        kreg[2 * k]     = f.x;
        kreg[2 * k + 1] = f.y;
    }

    float kv = 0.0f;
#pragma unroll
    for (int p = 0; p < 64; ++p) kv += kreg[p] * sv[p];
    float u = cfg::A_MARG / (kv + 1e-30f);

    if (j == cfg::ITERS) {
        if (act) g_u[n] = u;
        return;
    }
    float ua = act ? u : 0.0f;
#pragma unroll
    for (int p = 0; p < 64; ++p) kreg[p] *= ua;

    int lane = t & 31;
#pragma unroll
    for (int k = 0; k < 5; ++k) {
        int off = 16 >> k;
        int c   = 32 >> k;
        bool up = (lane & off) != 0;
#pragma unroll
        for (int i = 0; i < 32; ++i) {
            if (i < c) {
                float mine  = up ? kreg[i + c] : kreg[i];
                float other = up ? kreg[i]     : kreg[i + c];
                kreg[i] = mine + __shfl_xor_sync(0xffffffffu, other, off);
            }
        }
    }
    atomicAdd(&sKtu[2 * lane],     kreg[0]);
    atomicAdd(&sKtu[2 * lane + 1], kreg[1]);
    __syncthreads();
    if (t < cfg::P) atomicAdd(&g_KtuI[j][t], sKtu[t]);
}

// warp per node: prompt message, ot_loss, x_adapted -> out, xf(half) = l2norm.
// Reads only half2 K; reconstructs c = -0.1*ln(K).
__global__ void k_final(const float* __restrict__ x, const float* __restrict__ pt,
                        const float* __restrict__ alphap, float* __restrict__ out) {
    __shared__ float spt[cfg::P * cfg::D];
    __shared__ float sv[cfg::P];
    __shared__ float sLoss;
    for (int i = threadIdx.x; i < cfg::P * cfg::D; i += blockDim.x) spt[i] = pt[i];
    if (threadIdx.x < cfg::P) sv[threadIdx.x] = g_v[threadIdx.x];
    if (threadIdx.x == 0) sLoss = 0.0f;
    __syncthreads();
    float coef = (*alphap) * (float)cfg::N;
    int lane   = threadIdx.x & 31;
    int warpId = (blockIdx.x * blockDim.x + threadIdx.x) >> 5;
    int nWarps = (gridDim.x * blockDim.x) >> 5;
    const float4* spt4 = reinterpret_cast<const float4*>(spt);
    float lacc = 0.0f;
    for (int n = warpId; n < cfg::N; n += nWarps) {
        float u = g_u[n];
        float4 m = make_float4(0.f, 0.f, 0.f, 0.f);
        float lossn = 0.0f;
#pragma unroll 4
        for (int k = 0; k < 32; ++k) {
            unsigned raw = g_Kh[(size_t)k * cfg::N + n];   // warp broadcast
            float2 f = __half22float2(*reinterpret_cast<__half2*>(&raw));
            float kv0 = f.x * sv[2 * k];
            float kv1 = f.y * sv[2 * k + 1];
            float4 p0 = spt4[(2 * k) * 32 + lane];
            float4 p1 = spt4[(2 * k + 1) * 32 + lane];
            m.x += kv0 * p0.x + kv1 * p1.x;
            m.y += kv0 * p0.y + kv1 * p1.y;
            m.z += kv0 * p0.z + kv1 * p1.z;
            m.w += kv0 * p0.w + kv1 * p1.w;
            lossn += kv0 * (-0.1f * __logf(fmaxf(f.x, 1e-7f)))
                   + kv1 * (-0.1f * __logf(fmaxf(f.y, 1e-7f)));
        }
        lacc += u * lossn;
        float4 xv = reinterpret_cast<const float4*>(x + (size_t)n * cfg::D)[lane];
        float cu = coef * u;
        float4 xa = make_float4(xv.x + cu * m.x, xv.y + cu * m.y,
                                xv.z + cu * m.z, xv.w + cu * m.w);
        reinterpret_cast<float4*>(out + (size_t)n * cfg::D)[lane] = xa;
        float ss = warpAllReduceSum(xa.x * xa.x + xa.y * xa.y + xa.z * xa.z + xa.w * xa.w);
        float inv = 1.0f / fmaxf(sqrtf(ss), 1e-12f);
        __half2 h01 = __floats2half2_rn(xa.x * inv, xa.y * inv);
        __half2 h23 = __floats2half2_rn(xa.z * inv, xa.w * inv);
        uint2 pk;
        pk.x = *reinterpret_cast<unsigned*>(&h01);
        pk.y = *reinterpret_cast<unsigned*>(&h23);
        reinterpret_cast<uint2*>(g_xfh)[(size_t)n * 32 + lane] = pk;
    }
    if (lane == 0) atomicAdd(&sLoss, lacc);
    __syncthreads();
    if (threadIdx.x == 0) atomicAdd(&g_loss, sLoss);
}

__device__ __forceinline__ float dot8h(uint4 a, uint4 b) {
    const unsigned* pa = &a.x;
    const unsigned* pb = &b.x;
    float s = 0.0f;
#pragma unroll
    for (int i = 0; i < 4; ++i) {
        float2 fa = __half22float2(*reinterpret_cast<const __half2*>(pa + i));
        float2 fb = __half22float2(*reinterpret_cast<const __half2*>(pb + i));
        s += fa.x * fb.x + fa.y * fb.y;
    }
    return s;
}

// half-warp (16 lanes) per prompt-edge on fp16 xf: w = relu(dot); track max
__global__ void k_edge(const int* __restrict__ prow, const int* __restrict__ pcol,
                       float* __restrict__ outw) {
    __shared__ unsigned int smax;
    if (threadIdx.x == 0) smax = 0u;
    __syncthreads();
    int t    = threadIdx.x;
    int lane = t & 31;
    int sub  = lane >> 4;
    int sl   = lane & 15;
    int wid  = (blockIdx.x * blockDim.x + t) >> 5;
    int nW   = (gridDim.x * blockDim.x) >> 5;
    const uint4* xf4 = reinterpret_cast<const uint4*>(g_xfh);
    float lmax = 0.0f;
    for (int e0 = wid * 2; e0 < cfg::EPT; e0 += nW * 2) {
        int e = e0 + sub;
        float ts = 0.0f;
        bool act = (e < cfg::EPT);
        if (act) {
            int r = prow[e], c = pcol[e];
            uint4 av = __ldg(&xf4[(size_t)r * 16 + sl]);
            uint4 bv = __ldg(&xf4[(size_t)c * 16 + sl]);
            ts = dot8h(av, bv);
        }
#pragma unroll
        for (int o = 8; o; o >>= 1) ts += __shfl_xor_sync(0xffffffffu, ts, o);
        if (sl == 0 && act) {
            float wv = fmaxf(ts, 0.0f);
            outw[e] = wv;
            lmax = fmaxf(lmax, wv);
        }
    }
    atomicMax(&smax, __float_as_uint(lmax));
    __syncthreads();
    if (threadIdx.x == 0) atomicMax(&g_wmax, smax);
}

// scale w in place (vectorized; w base is only 4B-aligned: 3-elem prologue,
// float4 body, scalar tail); emit ot_loss
__global__ void k_scale(float* __restrict__ out) {
    float inv = 1.0f / (__uint_as_float(g_wmax) + 1e-8f);
    float* w = out + (size_t)cfg::N * cfg::D + 1;
    if (blockIdx.x == 0 && threadIdx.x == 0) {
        out[(size_t)cfg::N * cfg::D] = g_loss;
        w[0] *= inv; w[1] *= inv; w[2] *= inv;
        // tail: elements [3 + n4*4, EPT)
        constexpr size_t n4 = (size_t)(cfg::EPT - 3) / 4;
        for (size_t e = 3 + n4 * 4; e < (size_t)cfg::EPT; ++e) w[e] *= inv;
    }
    float4* w4 = reinterpret_cast<float4*>(w + 3);
    constexpr size_t n4 = (size_t)(cfg::EPT - 3) / 4;
    size_t idx    = (size_t)blockIdx.x * blockDim.x + threadIdx.x;
    size_t stride = (size_t)gridDim.x * blockDim.x;
    for (size_t i = idx; i < n4; i += stride) {
        float4 v = w4[i];
        v.x *= inv; v.y *= inv; v.z *= inv; v.w *= inv;
        w4[i] = v;
    }
}

// ---------------- launch ----------------
extern "C" void kernel_launch(void* const* d_in, const int* in_sizes, int n_in,
                              void* d_out, int out_size) {
    const float* x     = (const float*)d_in[0];
    const int*   ei    = (const int*)d_in[1];
    const float* ew    = (const float*)d_in[2];
    const int*   pei   = (const int*)d_in[3];
    const float* pt    = (const float*)d_in[4];
    const float* alpha = (const float*)d_in[5];
    const float* gamma = (const float*)d_in[6];
    float* out = (float*)d_out;

    const int* row  = ei;
    const int* col  = ei + cfg::E;
    const int* prow = pei;
    const int* pcol = pei + cfg::EPT;

    cudaFuncSetAttribute(k_ck, cudaFuncAttributeMaxDynamicSharedMemorySize, 98304);

    k_init<<<512, 256>>>(pt);
    k_count<<<(cfg::E + 255) / 256, 256>>>(row, col);
    k_node_xd<<<(cfg::N * 32 + 255) / 256, 256>>>(x);
    k_fill<<<(cfg::E + 255) / 256, 256>>>(row, col, ew);
    k_aggr<<<(cfg::N * 32 + 255) / 256, 256>>>();
    k_ck<<<(cfg::N + 127) / 128, 256, 98304>>>(x, gamma);   // includes Ktu0

    for (int j = 1; j <= cfg::ITERS; ++j)
        k_ua<<<(cfg::N + 255) / 256, 256>>>(j);

    k_final<<<2048, 256>>>(x, pt, alpha, out);
    k_edge<<<8192, 256>>>(prow, pcol, out + (size_t)cfg::N * cfg::D + 1);
    k_scale<<<4096, 256>>>(out);
}

// round 11
// speedup vs baseline: 1.1045x; 1.0813x over previous
#include <cuda_runtime.h>
#include <cuda_fp16.h>
#include <cstdint>

// ---------------- problem constants ----------------
namespace cfg {
constexpr int   N    = 100000;
constexpr int   D    = 128;
constexpr int   P    = 64;
constexpr int   E    = 3200000;
constexpr int   EPT  = 5000000;
constexpr float INV_EPS = 10.0f;           // 1/0.1
constexpr int   ITERS   = 20;
constexpr float A_MARG  = 1.0f / 100000.0f;
constexpr float B_MARG  = 1.0f / 64.0f;
}

// ---------------- device scratch (static, no allocs) ----------------
__device__ int   g_cnt[cfg::N];                      // row histogram (CSR)
__device__ int   g_degc[cfg::N];                     // col histogram (GCN deg)
__device__ float g_dis[cfg::N];                      // deg^-1/2
__device__ int   g_off[cfg::N];                      // CSR segment base
__device__ int   g_cursor[cfg::N];                   // CSR fill cursor
__device__ int2  g_epay[cfg::E];                     // CSR payload: (col, ew-bits)
__device__ int   g_total;                            // segment allocator
__device__ __half g_xd[(size_t)cfg::N * cfg::D];     // fp16 dis[c]*x[c] (gathers)
__device__ float g_aggr[(size_t)cfg::N * cfg::D];    // aggregation result
__device__ __half g_xfh[(size_t)cfg::N * cfg::D];    // normalized x_adapted (fp16)
__device__ unsigned g_Kh[(size_t)(cfg::P / 2) * cfg::N]; // half2 K: [k][n], p=(2k,2k+1)
__device__ float g_u[cfg::N];
__device__ float g_KtuI[cfg::ITERS + 1][cfg::P];     // per-iteration K^T u buffers
__device__ float g_v[cfg::P];
__device__ float g_pn[cfg::P * cfg::D];              // normalized prompts
__device__ float g_loss;
__device__ unsigned int g_wmax;

// ---------------- helpers ----------------
__device__ __forceinline__ float warpAllReduceSum(float v) {
#pragma unroll
    for (int o = 16; o; o >>= 1) v += __shfl_xor_sync(0xffffffffu, v, o);
    return v;
}

// ---------------- kernels ----------------

// fused: zero scratch + normalize prompt tokens (block 0)
__global__ void k_init(const float* __restrict__ pt) {
    size_t idx    = (size_t)blockIdx.x * blockDim.x + threadIdx.x;
    size_t stride = (size_t)gridDim.x * blockDim.x;
    for (size_t i = idx; i < (size_t)cfg::N; i += stride) { g_cnt[i] = 0; g_degc[i] = 0; }
    if (idx < (size_t)((cfg::ITERS + 1) * cfg::P))
        g_KtuI[idx / cfg::P][idx % cfg::P] = 0.0f;
    if (idx == 0) { g_loss = 0.0f; g_wmax = 0u; g_total = 0; }
    if (blockIdx.x == 0) {
        int lane = threadIdx.x & 31;
        int w    = threadIdx.x >> 5;
        for (int p = w; p < cfg::P; p += 8) {
            float4 v = reinterpret_cast<const float4*>(pt + (size_t)p * cfg::D)[lane];
            float ss = warpAllReduceSum(v.x * v.x + v.y * v.y + v.z * v.z + v.w * v.w);
            float inv = 1.0f / fmaxf(sqrtf(ss), 1e-12f);
            float4 o = make_float4(v.x * inv, v.y * inv, v.z * inv, v.w * inv);
            reinterpret_cast<float4*>(g_pn + (size_t)p * cfg::D)[lane] = o;
        }
    }
}

// histograms: row buckets (CSR) and col degree (GCN norm)
__global__ void k_count(const int* __restrict__ row, const int* __restrict__ col) {
    int i = blockIdx.x * blockDim.x + threadIdx.x;
    if (i < cfg::E) {
        atomicAdd(&g_cnt[row[i]], 1);
        atomicAdd(&g_degc[col[i]], 1);
    }
}

// per node: deg^-1/2 and CSR segment allocation (ticket; order irrelevant)
__global__ void k_node() {
    int i = blockIdx.x * blockDim.x + threadIdx.x;
    if (i < cfg::N) {
        int d = g_degc[i];
        g_dis[i] = (d > 0) ? rsqrtf((float)d) : 0.0f;
        int c = g_cnt[i];
        int base = atomicAdd(&g_total, c);
        g_off[i] = base;
        g_cursor[i] = base;
    }
}

// fp16 dis-prescaled copy of x: xd[n][d] = dis[n] * x[n][d]
__global__ void k_xd(const float* __restrict__ x) {
    size_t idx    = (size_t)blockIdx.x * blockDim.x + threadIdx.x;
    size_t stride = (size_t)gridDim.x * blockDim.x;
    const float4* x4 = reinterpret_cast<const float4*>(x);
    uint2* xd2 = reinterpret_cast<uint2*>(g_xd);
    size_t total = (size_t)cfg::N * cfg::D / 4;
    for (size_t i = idx; i < total; i += stride) {
        float dn = g_dis[i >> 5];      // 32 consecutive float4 per node
        float4 v = x4[i];
        __half2 h0 = __floats2half2_rn(v.x * dn, v.y * dn);
        __half2 h1 = __floats2half2_rn(v.z * dn, v.w * dn);
        uint2 pk;
        pk.x = *reinterpret_cast<unsigned*>(&h0);
        pk.y = *reinterpret_cast<unsigned*>(&h1);
        xd2[i] = pk;
    }
}

// per edge: drop (col, ew) payload into row's CSR segment (no dis fetches)
__global__ void k_fill(const int* __restrict__ row, const int* __restrict__ col,
                       const float* __restrict__ ew) {
    int i = blockIdx.x * blockDim.x + threadIdx.x;
    if (i < cfg::E) {
        int r = row[i];
        int pos = atomicAdd(&g_cursor[r], 1);
        g_epay[pos] = make_int2(col[i], __float_as_int(ew[i]));
    }
}

// warp per node: aggr = dis[n] * sum(ew * xd[col]) over node's CSR segment
__global__ void k_aggr() {
    int lane = threadIdx.x & 31;
    int n    = (blockIdx.x * blockDim.x + threadIdx.x) >> 5;
    if (n >= cfg::N) return;
    int base = g_off[n];
    int cnt  = g_cnt[n];
    const uint2* xd2 = reinterpret_cast<const uint2*>(g_xd);
    float4 a0 = make_float4(0.f, 0.f, 0.f, 0.f);
    float4 a1 = make_float4(0.f, 0.f, 0.f, 0.f);
    int j = 0;
    for (; j + 4 <= cnt; j += 4) {
        int2 p0 = g_epay[base + j];
        int2 p1 = g_epay[base + j + 1];
        int2 p2 = g_epay[base + j + 2];
        int2 p3 = g_epay[base + j + 3];
        uint2 r0 = __ldg(&xd2[(size_t)p0.x * 32 + lane]);
        uint2 r1 = __ldg(&xd2[(size_t)p1.x * 32 + lane]);
        uint2 r2 = __ldg(&xd2[(size_t)p2.x * 32 + lane]);
        uint2 r3 = __ldg(&xd2[(size_t)p3.x * 32 + lane]);
        float w0 = __int_as_float(p0.y), w1 = __int_as_float(p1.y);
        float w2 = __int_as_float(p2.y), w3 = __int_as_float(p3.y);
        float2 f;
        f = __half22float2(*reinterpret_cast<__half2*>(&r0.x)); a0.x += w0*f.x; a0.y += w0*f.y;
        f = __half22float2(*reinterpret_cast<__half2*>(&r0.y)); a0.z += w0*f.x; a0.w += w0*f.y;
        f = __half22float2(*reinterpret_cast<__half2*>(&r1.x)); a1.x += w1*f.x; a1.y += w1*f.y;
        f = __half22float2(*reinterpret_cast<__half2*>(&r1.y)); a1.z += w1*f.x; a1.w += w1*f.y;
        f = __half22float2(*reinterpret_cast<__half2*>(&r2.x)); a0.x += w2*f.x; a0.y += w2*f.y;
        f = __half22float2(*reinterpret_cast<__half2*>(&r2.y)); a0.z += w2*f.x; a0.w += w2*f.y;
        f = __half22float2(*reinterpret_cast<__half2*>(&r3.x)); a1.x += w3*f.x; a1.y += w3*f.y;
        f = __half22float2(*reinterpret_cast<__half2*>(&r3.y)); a1.z += w3*f.x; a1.w += w3*f.y;
    }
    for (; j < cnt; ++j) {
        int2 p0 = g_epay[base + j];
        uint2 r0 = __ldg(&xd2[(size_t)p0.x * 32 + lane]);
        float w0 = __int_as_float(p0.y);
        float2 f;
        f = __half22float2(*reinterpret_cast<__half2*>(&r0.x)); a0.x += w0*f.x; a0.y += w0*f.y;
        f = __half22float2(*reinterpret_cast<__half2*>(&r0.y)); a0.z += w0*f.x; a0.w += w0*f.y;
    }
    float dn = g_dis[n];
    float4 acc = make_float4(dn * (a0.x + a1.x), dn * (a0.y + a1.y),
                             dn * (a0.z + a1.z), dn * (a0.w + a1.w));
    reinterpret_cast<float4*>(g_aggr)[(size_t)n * 32 + lane] = acc;
}

// Fused: per block of 128 nodes, build normalized xs in swizzled smem, then
// register-tiled GEMM against pn -> packed half2 K [32][N]; fused Ktu0.
__global__ void k_ck(const float* __restrict__ x, const float* __restrict__ gammap) {
    extern __shared__ float sm[];
    float* xs_s = sm;            // 128*128
    float* pn_s = sm + 16384;    // 128*64
    int t  = threadIdx.x;
    int nb = blockIdx.x * 128;
    float gm = *gammap;

    for (int idx = t; idx < cfg::P * cfg::D; idx += 256) {
        int p = idx >> 7, d = idx & 127;
        pn_s[d * 64 + p] = g_pn[idx];
    }

    int lane = t & 31, w = t >> 5;
    for (int it = 0; it < 16; ++it) {
        int nl = w + 8 * it;
        int n  = nb + nl;
        bool act = (n < cfg::N);
        float xs[4];
        float ss = 0.0f;
#pragma unroll
        for (int m = 0; m < 4; ++m) {
            int d = lane + 32 * m;
            float xv = act ? x[(size_t)n * 128 + d] : 0.0f;
            float ag = act ? g_aggr[(size_t)n * 128 + d] : 0.0f;
            xs[m] = (1.0f - gm) * xv + gm * ag;
            ss += xs[m] * xs[m];
        }
        ss = warpAllReduceSum(ss);
        float inv = 1.0f / fmaxf(sqrtf(ss), 1e-12f);
#pragma unroll
        for (int m = 0; m < 4; ++m) {
            int d = lane + 32 * m;
            xs_s[d * 128 + ((nl + d) & 127)] = xs[m] * inv;
        }
    }
    __syncthreads();

    int tx = t & 31, ty = t >> 5;
    float acc[4][8];
#pragma unroll
    for (int i = 0; i < 4; ++i)
#pragma unroll
        for (int j = 0; j < 8; ++j) acc[i][j] = 0.0f;

#pragma unroll 4
    for (int k = 0; k < 128; ++k) {
        float a[4];
#pragma unroll
        for (int i = 0; i < 4; ++i)
            a[i] = xs_s[k * 128 + ((tx + 32 * i + k) & 127)];
        float b[8];
#pragma unroll
        for (int j = 0; j < 8; ++j)
            b[j] = pn_s[k * 64 + ty * 8 + j];
#pragma unroll
        for (int i = 0; i < 4; ++i)
#pragma unroll
            for (int j = 0; j < 8; ++j)
                acc[i][j] += a[i] * b[j];
    }

    // epilogue: K = exp((s-1)*10) -> half2 [32][N]; accumulate Ktu0
    float ksum[8];
#pragma unroll
    for (int j = 0; j < 8; ++j) ksum[j] = 0.0f;
#pragma unroll
    for (int i = 0; i < 4; ++i) {
        int n = nb + tx + 32 * i;
        bool act = (n < cfg::N);
        float kv[8];
#pragma unroll
        for (int j = 0; j < 8; ++j) {
            kv[j] = __expf((acc[i][j] - 1.0f) * cfg::INV_EPS);
            if (act) ksum[j] += kv[j];
        }
        if (act) {
#pragma unroll
            for (int m = 0; m < 4; ++m) {
                __half2 h = __floats2half2_rn(kv[2 * m], kv[2 * m + 1]);
                g_Kh[(size_t)(ty * 4 + m) * cfg::N + n] = *reinterpret_cast<unsigned*>(&h);
            }
        }
    }
#pragma unroll
    for (int j = 0; j < 8; ++j) {
        float tot = warpAllReduceSum(ksum[j]);
        if (tx == 0) atomicAdd(&g_KtuI[0][ty * 8 + j], cfg::A_MARG * tot);
    }
}

// One Sinkhorn pass per launch, j=1..20: v = b/Ktu[j-1]; u = a/(K v);
// j<20: Ktu[j] = K^T u. j=20: store u (and v).
__global__ void k_ua(int j) {
    __shared__ float sv[cfg::P];
    __shared__ float sKtu[cfg::P];
    int t = threadIdx.x;
    if (t < cfg::P) {
        sKtu[t] = 0.0f;
        float v = cfg::B_MARG / (g_KtuI[j - 1][t] + 1e-30f);
        sv[t] = v;
        if (j == cfg::ITERS && blockIdx.x == 0) g_v[t] = v;
    }
    __syncthreads();

    int n = blockIdx.x * 256 + t;
    bool act = (n < cfg::N);
    int nn = act ? n : 0;

    float kreg[64];
#pragma unroll
    for (int k = 0; k < 32; ++k) {
        unsigned raw = g_Kh[(size_t)k * cfg::N + nn];
        float2 f = __half22float2(*reinterpret_cast<__half2*>(&raw));
        kreg[2 * k]     = f.x;
        kreg[2 * k + 1] = f.y;
    }

    float kv = 0.0f;
#pragma unroll
    for (int p = 0; p < 64; ++p) kv += kreg[p] * sv[p];
    float u = cfg::A_MARG / (kv + 1e-30f);

    if (j == cfg::ITERS) {
        if (act) g_u[n] = u;
        return;
    }
    float ua = act ? u : 0.0f;
#pragma unroll
    for (int p = 0; p < 64; ++p) kreg[p] *= ua;

    int lane = t & 31;
#pragma unroll
    for (int k = 0; k < 5; ++k) {
        int off = 16 >> k;
        int c   = 32 >> k;
        bool up = (lane & off) != 0;
#pragma unroll
        for (int i = 0; i < 32; ++i) {
            if (i < c) {
                float mine  = up ? kreg[i + c] : kreg[i];
                float other = up ? kreg[i]     : kreg[i + c];
                kreg[i] = mine + __shfl_xor_sync(0xffffffffu, other, off);
            }
        }
    }
    atomicAdd(&sKtu[2 * lane],     kreg[0]);
    atomicAdd(&sKtu[2 * lane + 1], kreg[1]);
    __syncthreads();
    if (t < cfg::P) atomicAdd(&g_KtuI[j][t], sKtu[t]);
}

// warp per node: prompt message, ot_loss, x_adapted -> out, xf(half) = l2norm.
// Loss logs are lane-sliced: lane l handles k=l (2 logs/warp-instr path instead
// of 64 redundant warp-wide MUFU ops); values are L1-hits from the main loop.
__global__ void k_final(const float* __restrict__ x, const float* __restrict__ pt,
                        const float* __restrict__ alphap, float* __restrict__ out) {
    __shared__ float spt[cfg::P * cfg::D];
    __shared__ float sv[cfg::P];
    __shared__ float sLoss;
    for (int i = threadIdx.x; i < cfg::P * cfg::D; i += blockDim.x) spt[i] = pt[i];
    if (threadIdx.x < cfg::P) sv[threadIdx.x] = g_v[threadIdx.x];
    if (threadIdx.x == 0) sLoss = 0.0f;
    __syncthreads();
    float coef = (*alphap) * (float)cfg::N;
    int lane   = threadIdx.x & 31;
    int warpId = (blockIdx.x * blockDim.x + threadIdx.x) >> 5;
    int nWarps = (gridDim.x * blockDim.x) >> 5;
    const float4* spt4 = reinterpret_cast<const float4*>(spt);
    float lacc = 0.0f;
    for (int n = warpId; n < cfg::N; n += nWarps) {
        float u = g_u[n];
        float4 m = make_float4(0.f, 0.f, 0.f, 0.f);
#pragma unroll 4
        for (int k = 0; k < 32; ++k) {
            unsigned raw = g_Kh[(size_t)k * cfg::N + n];   // warp broadcast
            float2 f = __half22float2(*reinterpret_cast<__half2*>(&raw));
            float kv0 = f.x * sv[2 * k];
            float kv1 = f.y * sv[2 * k + 1];
            float4 p0 = spt4[(2 * k) * 32 + lane];
            float4 p1 = spt4[(2 * k + 1) * 32 + lane];
            m.x += kv0 * p0.x + kv1 * p1.x;
            m.y += kv0 * p0.y + kv1 * p1.y;
            m.z += kv0 * p0.z + kv1 * p1.z;
            m.w += kv0 * p0.w + kv1 * p1.w;
        }
        // loss: lane l computes only its own k=l pair (L1-hit reload)
        {
            unsigned rawl = g_Kh[(size_t)lane * cfg::N + n];
            float2 fl = __half22float2(*reinterpret_cast<__half2*>(&rawl));
            float part = fl.x * sv[2 * lane]     * (-0.1f * __logf(fmaxf(fl.x, 1e-7f)))
                       + fl.y * sv[2 * lane + 1] * (-0.1f * __logf(fmaxf(fl.y, 1e-7f)));
            part = warpAllReduceSum(part);
            lacc += u * part;                    // identical on all lanes
        }
        float4 xv = reinterpret_cast<const float4*>(x + (size_t)n * cfg::D)[lane];
        float cu = coef * u;
        float4 xa = make_float4(xv.x + cu * m.x, xv.y + cu * m.y,
                                xv.z + cu * m.z, xv.w + cu * m.w);
        reinterpret_cast<float4*>(out + (size_t)n * cfg::D)[lane] = xa;
        float ss = warpAllReduceSum(xa.x * xa.x + xa.y * xa.y + xa.z * xa.z + xa.w * xa.w);
        float inv = 1.0f / fmaxf(sqrtf(ss), 1e-12f);
        __half2 h01 = __floats2half2_rn(xa.x * inv, xa.y * inv);
        __half2 h23 = __floats2half2_rn(xa.z * inv, xa.w * inv);
        uint2 pk;
        pk.x = *reinterpret_cast<unsigned*>(&h01);
        pk.y = *reinterpret_cast<unsigned*>(&h23);
        reinterpret_cast<uint2*>(g_xfh)[(size_t)n * 32 + lane] = pk;
    }
    if (lane == 0) atomicAdd(&sLoss, lacc);
    __syncthreads();
    if (threadIdx.x == 0) atomicAdd(&g_loss, sLoss);
}

__device__ __forceinline__ float dot8h(uint4 a, uint4 b) {
    const unsigned* pa = &a.x;
    const unsigned* pb = &b.x;
    float s = 0.0f;
#pragma unroll
    for (int i = 0; i < 4; ++i) {
        float2 fa = __half22float2(*reinterpret_cast<const __half2*>(pa + i));
        float2 fb = __half22float2(*reinterpret_cast<const __half2*>(pb + i));
        s += fa.x * fb.x + fa.y * fb.y;
    }
    return s;
}

// half-warp (16 lanes) per prompt-edge on fp16 xf: w = relu(dot); track max
__global__ void k_edge(const int* __restrict__ prow, const int* __restrict__ pcol,
                       float* __restrict__ outw) {
    __shared__ unsigned int smax;
    if (threadIdx.x == 0) smax = 0u;
    __syncthreads();
    int t    = threadIdx.x;
    int lane = t & 31;
    int sub  = lane >> 4;
    int sl   = lane & 15;
    int wid  = (blockIdx.x * blockDim.x + t) >> 5;
    int nW   = (gridDim.x * blockDim.x) >> 5;
    const uint4* xf4 = reinterpret_cast<const uint4*>(g_xfh);
    float lmax = 0.0f;
    for (int e0 = wid * 2; e0 < cfg::EPT; e0 += nW * 2) {
        int e = e0 + sub;
        float ts = 0.0f;
        bool act = (e < cfg::EPT);
        if (act) {
            int r = prow[e], c = pcol[e];
            uint4 av = __ldg(&xf4[(size_t)r * 16 + sl]);
            uint4 bv = __ldg(&xf4[(size_t)c * 16 + sl]);
            ts = dot8h(av, bv);
        }
#pragma unroll
        for (int o = 8; o; o >>= 1) ts += __shfl_xor_sync(0xffffffffu, ts, o);
        if (sl == 0 && act) {
            float wv = fmaxf(ts, 0.0f);
            outw[e] = wv;
            lmax = fmaxf(lmax, wv);
        }
    }
    atomicMax(&smax, __float_as_uint(lmax));
    __syncthreads();
    if (threadIdx.x == 0) atomicMax(&g_wmax, smax);
}

// scale w in place; emit ot_loss
__global__ void k_scale(float* __restrict__ out) {
    float inv = 1.0f / (__uint_as_float(g_wmax) + 1e-8f);
    float* w = out + (size_t)cfg::N * cfg::D + 1;
    size_t idx    = (size_t)blockIdx.x * blockDim.x + threadIdx.x;
    size_t stride = (size_t)gridDim.x * blockDim.x;
    for (size_t e = idx; e < (size_t)cfg::EPT; e += stride) w[e] *= inv;
    if (blockIdx.x == 0 && threadIdx.x == 0) out[(size_t)cfg::N * cfg::D] = g_loss;
}

// ---------------- launch ----------------
extern "C" void kernel_launch(void* const* d_in, const int* in_sizes, int n_in,
                              void* d_out, int out_size) {
    const float* x     = (const float*)d_in[0];
    const int*   ei    = (const int*)d_in[1];
    const float* ew    = (const float*)d_in[2];
    const int*   pei   = (const int*)d_in[3];
    const float* pt    = (const float*)d_in[4];
    const float* alpha = (const float*)d_in[5];
    const float* gamma = (const float*)d_in[6];
    float* out = (float*)d_out;

    const int* row  = ei;
    const int* col  = ei + cfg::E;
    const int* prow = pei;
    const int* pcol = pei + cfg::EPT;

    cudaFuncSetAttribute(k_ck, cudaFuncAttributeMaxDynamicSharedMemorySize, 98304);

    k_init<<<512, 256>>>(pt);
    k_count<<<(cfg::E + 255) / 256, 256>>>(row, col);
    k_node<<<(cfg::N + 255) / 256, 256>>>();
    k_xd<<<2048, 256>>>(x);
    k_fill<<<(cfg::E + 255) / 256, 256>>>(row, col, ew);
    k_aggr<<<(cfg::N * 32 + 255) / 256, 256>>>();
    k_ck<<<(cfg::N + 127) / 128, 256, 98304>>>(x, gamma);   // includes Ktu0

    for (int j = 1; j <= cfg::ITERS; ++j)
        k_ua<<<(cfg::N + 255) / 256, 256>>>(j);

    k_final<<<2048, 256>>>(x, pt, alpha, out);
    k_edge<<<8192, 256>>>(prow, pcol, out + (size_t)cfg::N * cfg::D + 1);
    k_scale<<<4096, 256>>>(out);
}

// round 12
// speedup vs baseline: 1.1102x; 1.0052x over previous
#include <cuda_runtime.h>
#include <cuda_fp16.h>
#include <cstdint>

// ---------------- problem constants ----------------
namespace cfg {
constexpr int   N    = 100000;
constexpr int   D    = 128;
constexpr int   P    = 64;
constexpr int   E    = 3200000;
constexpr int   EPT  = 5000000;
constexpr float INV_EPS = 10.0f;           // 1/0.1
constexpr int   ITERS   = 20;
constexpr float A_MARG  = 1.0f / 100000.0f;
constexpr float B_MARG  = 1.0f / 64.0f;
}

// ---------------- device scratch (static, no allocs) ----------------
__device__ int   g_cnt[cfg::N];                      // row histogram (CSR)
__device__ int   g_degc[cfg::N];                     // col histogram (GCN deg)
__device__ float g_dis[cfg::N];                      // deg^-1/2
__device__ int   g_off[cfg::N];                      // CSR segment base
__device__ int   g_cursor[cfg::N];                   // CSR fill cursor
__device__ int2  g_epay[cfg::E];                     // CSR payload: (col, ew-bits)
__device__ int   g_total;                            // segment allocator
__device__ __half g_xd[(size_t)cfg::N * cfg::D];     // fp16 dis[c]*x[c] (gathers)
__device__ float g_aggr[(size_t)cfg::N * cfg::D];    // aggregation result
__device__ __half g_xfh[(size_t)cfg::N * cfg::D];    // normalized x_adapted (fp16)
__device__ unsigned g_Kh[(size_t)(cfg::P / 2) * cfg::N]; // half2 K: [k][n], p=(2k,2k+1)
__device__ float g_u[cfg::N];
__device__ float g_KtuI[cfg::ITERS + 1][cfg::P];     // per-iteration K^T u buffers
__device__ float g_v[cfg::P];
__device__ float g_pn[cfg::P * cfg::D];              // normalized prompts
__device__ float g_loss;
__device__ unsigned int g_wmax;

// ---------------- helpers ----------------
__device__ __forceinline__ float warpAllReduceSum(float v) {
#pragma unroll
    for (int o = 16; o; o >>= 1) v += __shfl_xor_sync(0xffffffffu, v, o);
    return v;
}

// ---------------- kernels ----------------

// fused: zero scratch + normalize prompt tokens (block 0)
__global__ void k_init(const float* __restrict__ pt) {
    size_t idx    = (size_t)blockIdx.x * blockDim.x + threadIdx.x;
    size_t stride = (size_t)gridDim.x * blockDim.x;
    for (size_t i = idx; i < (size_t)cfg::N; i += stride) { g_cnt[i] = 0; g_degc[i] = 0; }
    if (idx < (size_t)((cfg::ITERS + 1) * cfg::P))
        g_KtuI[idx / cfg::P][idx % cfg::P] = 0.0f;
    if (idx == 0) { g_loss = 0.0f; g_wmax = 0u; g_total = 0; }
    if (blockIdx.x == 0) {
        int lane = threadIdx.x & 31;
        int w    = threadIdx.x >> 5;
        for (int p = w; p < cfg::P; p += 8) {
            float4 v = reinterpret_cast<const float4*>(pt + (size_t)p * cfg::D)[lane];
            float ss = warpAllReduceSum(v.x * v.x + v.y * v.y + v.z * v.z + v.w * v.w);
            float inv = 1.0f / fmaxf(sqrtf(ss), 1e-12f);
            float4 o = make_float4(v.x * inv, v.y * inv, v.z * inv, v.w * inv);
            reinterpret_cast<float4*>(g_pn + (size_t)p * cfg::D)[lane] = o;
        }
    }
}

// histograms: row buckets (CSR) and col degree (GCN norm)
__global__ void k_count(const int* __restrict__ row, const int* __restrict__ col) {
    int i = blockIdx.x * blockDim.x + threadIdx.x;
    if (i < cfg::E) {
        atomicAdd(&g_cnt[row[i]], 1);
        atomicAdd(&g_degc[col[i]], 1);
    }
}

// per node: deg^-1/2 and CSR segment allocation (ticket; order irrelevant)
__global__ void k_node() {
    int i = blockIdx.x * blockDim.x + threadIdx.x;
    if (i < cfg::N) {
        int d = g_degc[i];
        g_dis[i] = (d > 0) ? rsqrtf((float)d) : 0.0f;
        int c = g_cnt[i];
        int base = atomicAdd(&g_total, c);
        g_off[i] = base;
        g_cursor[i] = base;
    }
}

// fp16 dis-prescaled copy of x: xd[n][d] = dis[n] * x[n][d]
__global__ void k_xd(const float* __restrict__ x) {
    size_t idx    = (size_t)blockIdx.x * blockDim.x + threadIdx.x;
    size_t stride = (size_t)gridDim.x * blockDim.x;
    const float4* x4 = reinterpret_cast<const float4*>(x);
    uint2* xd2 = reinterpret_cast<uint2*>(g_xd);
    size_t total = (size_t)cfg::N * cfg::D / 4;
    for (size_t i = idx; i < total; i += stride) {
        float dn = g_dis[i >> 5];      // 32 consecutive float4 per node
        float4 v = x4[i];
        __half2 h0 = __floats2half2_rn(v.x * dn, v.y * dn);
        __half2 h1 = __floats2half2_rn(v.z * dn, v.w * dn);
        uint2 pk;
        pk.x = *reinterpret_cast<unsigned*>(&h0);
        pk.y = *reinterpret_cast<unsigned*>(&h1);
        xd2[i] = pk;
    }
}

// per edge: drop (col, ew) payload into row's CSR segment (no dis fetches)
__global__ void k_fill(const int* __restrict__ row, const int* __restrict__ col,
                       const float* __restrict__ ew) {
    int i = blockIdx.x * blockDim.x + threadIdx.x;
    if (i < cfg::E) {
        int r = row[i];
        int pos = atomicAdd(&g_cursor[r], 1);
        g_epay[pos] = make_int2(col[i], __float_as_int(ew[i]));
    }
}

// warp per node: aggr = dis[n] * sum(ew * xd[col]) over node's CSR segment
__global__ void k_aggr() {
    int lane = threadIdx.x & 31;
    int n    = (blockIdx.x * blockDim.x + threadIdx.x) >> 5;
    if (n >= cfg::N) return;
    int base = g_off[n];
    int cnt  = g_cnt[n];
    const uint2* xd2 = reinterpret_cast<const uint2*>(g_xd);
    float4 a0 = make_float4(0.f, 0.f, 0.f, 0.f);
    float4 a1 = make_float4(0.f, 0.f, 0.f, 0.f);
    int j = 0;
    for (; j + 4 <= cnt; j += 4) {
        int2 p0 = g_epay[base + j];
        int2 p1 = g_epay[base + j + 1];
        int2 p2 = g_epay[base + j + 2];
        int2 p3 = g_epay[base + j + 3];
        uint2 r0 = __ldg(&xd2[(size_t)p0.x * 32 + lane]);
        uint2 r1 = __ldg(&xd2[(size_t)p1.x * 32 + lane]);
        uint2 r2 = __ldg(&xd2[(size_t)p2.x * 32 + lane]);
        uint2 r3 = __ldg(&xd2[(size_t)p3.x * 32 + lane]);
        float w0 = __int_as_float(p0.y), w1 = __int_as_float(p1.y);
        float w2 = __int_as_float(p2.y), w3 = __int_as_float(p3.y);
        float2 f;
        f = __half22float2(*reinterpret_cast<__half2*>(&r0.x)); a0.x += w0*f.x; a0.y += w0*f.y;
        f = __half22float2(*reinterpret_cast<__half2*>(&r0.y)); a0.z += w0*f.x; a0.w += w0*f.y;
        f = __half22float2(*reinterpret_cast<__half2*>(&r1.x)); a1.x += w1*f.x; a1.y += w1*f.y;
        f = __half22float2(*reinterpret_cast<__half2*>(&r1.y)); a1.z += w1*f.x; a1.w += w1*f.y;
        f = __half22float2(*reinterpret_cast<__half2*>(&r2.x)); a0.x += w2*f.x; a0.y += w2*f.y;
        f = __half22float2(*reinterpret_cast<__half2*>(&r2.y)); a0.z += w2*f.x; a0.w += w2*f.y;
        f = __half22float2(*reinterpret_cast<__half2*>(&r3.x)); a1.x += w3*f.x; a1.y += w3*f.y;
        f = __half22float2(*reinterpret_cast<__half2*>(&r3.y)); a1.z += w3*f.x; a1.w += w3*f.y;
    }
    for (; j < cnt; ++j) {
        int2 p0 = g_epay[base + j];
        uint2 r0 = __ldg(&xd2[(size_t)p0.x * 32 + lane]);
        float w0 = __int_as_float(p0.y);
        float2 f;
        f = __half22float2(*reinterpret_cast<__half2*>(&r0.x)); a0.x += w0*f.x; a0.y += w0*f.y;
        f = __half22float2(*reinterpret_cast<__half2*>(&r0.y)); a0.z += w0*f.x; a0.w += w0*f.y;
    }
    float dn = g_dis[n];
    float4 acc = make_float4(dn * (a0.x + a1.x), dn * (a0.y + a1.y),
                             dn * (a0.z + a1.z), dn * (a0.w + a1.w));
    reinterpret_cast<float4*>(g_aggr)[(size_t)n * 32 + lane] = acc;
}

// Fused: per block of 128 nodes, build normalized xs in swizzled smem, then
// register-tiled GEMM against pn -> packed half2 K [32][N]; fused Ktu0.
__global__ void k_ck(const float* __restrict__ x, const float* __restrict__ gammap) {
    extern __shared__ float sm[];
    float* xs_s = sm;            // 128*128
    float* pn_s = sm + 16384;    // 128*64
    int t  = threadIdx.x;
    int nb = blockIdx.x * 128;
    float gm = *gammap;

    for (int idx = t; idx < cfg::P * cfg::D; idx += 256) {
        int p = idx >> 7, d = idx & 127;
        pn_s[d * 64 + p] = g_pn[idx];
    }

    int lane = t & 31, w = t >> 5;
    for (int it = 0; it < 16; ++it) {
        int nl = w + 8 * it;
        int n  = nb + nl;
        bool act = (n < cfg::N);
        float xs[4];
        float ss = 0.0f;
#pragma unroll
        for (int m = 0; m < 4; ++m) {
            int d = lane + 32 * m;
            float xv = act ? x[(size_t)n * 128 + d] : 0.0f;
            float ag = act ? g_aggr[(size_t)n * 128 + d] : 0.0f;
            xs[m] = (1.0f - gm) * xv + gm * ag;
            ss += xs[m] * xs[m];
        }
        ss = warpAllReduceSum(ss);
        float inv = 1.0f / fmaxf(sqrtf(ss), 1e-12f);
#pragma unroll
        for (int m = 0; m < 4; ++m) {
            int d = lane + 32 * m;
            xs_s[d * 128 + ((nl + d) & 127)] = xs[m] * inv;
        }
    }
    __syncthreads();

    int tx = t & 31, ty = t >> 5;
    float acc[4][8];
#pragma unroll
    for (int i = 0; i < 4; ++i)
#pragma unroll
        for (int j = 0; j < 8; ++j) acc[i][j] = 0.0f;

#pragma unroll 4
    for (int k = 0; k < 128; ++k) {
        float a[4];
#pragma unroll
        for (int i = 0; i < 4; ++i)
            a[i] = xs_s[k * 128 + ((tx + 32 * i + k) & 127)];
        float b[8];
#pragma unroll
        for (int j = 0; j < 8; ++j)
            b[j] = pn_s[k * 64 + ty * 8 + j];
#pragma unroll
        for (int i = 0; i < 4; ++i)
#pragma unroll
            for (int j = 0; j < 8; ++j)
                acc[i][j] += a[i] * b[j];
    }

    // epilogue: K = exp((s-1)*10) -> half2 [32][N]; accumulate Ktu0
    float ksum[8];
#pragma unroll
    for (int j = 0; j < 8; ++j) ksum[j] = 0.0f;
#pragma unroll
    for (int i = 0; i < 4; ++i) {
        int n = nb + tx + 32 * i;
        bool act = (n < cfg::N);
        float kv[8];
#pragma unroll
        for (int j = 0; j < 8; ++j) {
            kv[j] = __expf((acc[i][j] - 1.0f) * cfg::INV_EPS);
            if (act) ksum[j] += kv[j];
        }
        if (act) {
#pragma unroll
            for (int m = 0; m < 4; ++m) {
                __half2 h = __floats2half2_rn(kv[2 * m], kv[2 * m + 1]);
                g_Kh[(size_t)(ty * 4 + m) * cfg::N + n] = *reinterpret_cast<unsigned*>(&h);
            }
        }
    }
#pragma unroll
    for (int j = 0; j < 8; ++j) {
        float tot = warpAllReduceSum(ksum[j]);
        if (tx == 0) atomicAdd(&g_KtuI[0][ty * 8 + j], cfg::A_MARG * tot);
    }
}

// One Sinkhorn pass per launch, j=1..20: v = b/Ktu[j-1]; u = a/(K v);
// j<20: Ktu[j] = K^T u. j=20: store u (and v).
__global__ void k_ua(int j) {
    __shared__ float sv[cfg::P];
    __shared__ float sKtu[cfg::P];
    int t = threadIdx.x;
    if (t < cfg::P) {
        sKtu[t] = 0.0f;
        float v = cfg::B_MARG / (g_KtuI[j - 1][t] + 1e-30f);
        sv[t] = v;
        if (j == cfg::ITERS && blockIdx.x == 0) g_v[t] = v;
    }
    __syncthreads();

    int n = blockIdx.x * 256 + t;
    bool act = (n < cfg::N);
    int nn = act ? n : 0;

    float kreg[64];
#pragma unroll
    for (int k = 0; k < 32; ++k) {
        unsigned raw = g_Kh[(size_t)k * cfg::N + nn];
        float2 f = __half22float2(*reinterpret_cast<__half2*>(&raw));
        kreg[2 * k]     = f.x;
        kreg[2 * k + 1] = f.y;
    }

    float kv = 0.0f;
#pragma unroll
    for (int p = 0; p < 64; ++p) kv += kreg[p] * sv[p];
    float u = cfg::A_MARG / (kv + 1e-30f);

    if (j == cfg::ITERS) {
        if (act) g_u[n] = u;
        return;
    }
    float ua = act ? u : 0.0f;
#pragma unroll
    for (int p = 0; p < 64; ++p) kreg[p] *= ua;

    int lane = t & 31;
#pragma unroll
    for (int k = 0; k < 5; ++k) {
        int off = 16 >> k;
        int c   = 32 >> k;
        bool up = (lane & off) != 0;
#pragma unroll
        for (int i = 0; i < 32; ++i) {
            if (i < c) {
                float mine  = up ? kreg[i + c] : kreg[i];
                float other = up ? kreg[i]     : kreg[i + c];
                kreg[i] = mine + __shfl_xor_sync(0xffffffffu, other, off);
            }
        }
    }
    atomicAdd(&sKtu[2 * lane],     kreg[0]);
    atomicAdd(&sKtu[2 * lane + 1], kreg[1]);
    __syncthreads();
    if (t < cfg::P) atomicAdd(&g_KtuI[j][t], sKtu[t]);
}

// warp per node: prompt message, ot_loss, x_adapted -> out, xf(half) = l2norm.
// Loss logs are lane-sliced: lane l handles k=l (L1-hit reload, 2 logs).
__global__ void k_final(const float* __restrict__ x, const float* __restrict__ pt,
                        const float* __restrict__ alphap, float* __restrict__ out) {
    __shared__ float spt[cfg::P * cfg::D];
    __shared__ float sv[cfg::P];
    __shared__ float sLoss;
    for (int i = threadIdx.x; i < cfg::P * cfg::D; i += blockDim.x) spt[i] = pt[i];
    if (threadIdx.x < cfg::P) sv[threadIdx.x] = g_v[threadIdx.x];
    if (threadIdx.x == 0) sLoss = 0.0f;
    __syncthreads();
    float coef = (*alphap) * (float)cfg::N;
    int lane   = threadIdx.x & 31;
    int warpId = (blockIdx.x * blockDim.x + threadIdx.x) >> 5;
    int nWarps = (gridDim.x * blockDim.x) >> 5;
    const float4* spt4 = reinterpret_cast<const float4*>(spt);
    float lacc = 0.0f;
    for (int n = warpId; n < cfg::N; n += nWarps) {
        float u = g_u[n];
        float4 m = make_float4(0.f, 0.f, 0.f, 0.f);
#pragma unroll 4
        for (int k = 0; k < 32; ++k) {
            unsigned raw = g_Kh[(size_t)k * cfg::N + n];   // warp broadcast
            float2 f = __half22float2(*reinterpret_cast<__half2*>(&raw));
            float kv0 = f.x * sv[2 * k];
            float kv1 = f.y * sv[2 * k + 1];
            float4 p0 = spt4[(2 * k) * 32 + lane];
            float4 p1 = spt4[(2 * k + 1) * 32 + lane];
            m.x += kv0 * p0.x + kv1 * p1.x;
            m.y += kv0 * p0.y + kv1 * p1.y;
            m.z += kv0 * p0.z + kv1 * p1.z;
            m.w += kv0 * p0.w + kv1 * p1.w;
        }
        // loss: lane l computes only its own k=l pair (L1-hit reload)
        {
            unsigned rawl = g_Kh[(size_t)lane * cfg::N + n];
            float2 fl = __half22float2(*reinterpret_cast<__half2*>(&rawl));
            float part = fl.x * sv[2 * lane]     * (-0.1f * __logf(fmaxf(fl.x, 1e-7f)))
                       + fl.y * sv[2 * lane + 1] * (-0.1f * __logf(fmaxf(fl.y, 1e-7f)));
            part = warpAllReduceSum(part);
            lacc += u * part;                    // identical on all lanes
        }
        float4 xv = reinterpret_cast<const float4*>(x + (size_t)n * cfg::D)[lane];
        float cu = coef * u;
        float4 xa = make_float4(xv.x + cu * m.x, xv.y + cu * m.y,
                                xv.z + cu * m.z, xv.w + cu * m.w);
        reinterpret_cast<float4*>(out + (size_t)n * cfg::D)[lane] = xa;
        float ss = warpAllReduceSum(xa.x * xa.x + xa.y * xa.y + xa.z * xa.z + xa.w * xa.w);
        float inv = 1.0f / fmaxf(sqrtf(ss), 1e-12f);
        __half2 h01 = __floats2half2_rn(xa.x * inv, xa.y * inv);
        __half2 h23 = __floats2half2_rn(xa.z * inv, xa.w * inv);
        uint2 pk;
        pk.x = *reinterpret_cast<unsigned*>(&h01);
        pk.y = *reinterpret_cast<unsigned*>(&h23);
        reinterpret_cast<uint2*>(g_xfh)[(size_t)n * 32 + lane] = pk;
    }
    if (lane == 0) atomicAdd(&sLoss, lacc);
    __syncthreads();
    if (threadIdx.x == 0) atomicAdd(&g_loss, sLoss);
}

__device__ __forceinline__ float dot8h(uint4 a, uint4 b) {
    const unsigned* pa = &a.x;
    const unsigned* pb = &b.x;
    float s = 0.0f;
#pragma unroll
    for (int i = 0; i < 4; ++i) {
        float2 fa = __half22float2(*reinterpret_cast<const __half2*>(pa + i));
        float2 fb = __half22float2(*reinterpret_cast<const __half2*>(pb + i));
        s += fa.x * fb.x + fa.y * fb.y;
    }
    return s;
}

// half-warp (16 lanes) per prompt-edge on fp16 xf: w = relu(dot); track max
__global__ void k_edge(const int* __restrict__ prow, const int* __restrict__ pcol,
                       float* __restrict__ outw) {
    __shared__ unsigned int smax;
    if (threadIdx.x == 0) smax = 0u;
    __syncthreads();
    int t    = threadIdx.x;
    int lane = t & 31;
    int sub  = lane >> 4;
    int sl   = lane & 15;
    int wid  = (blockIdx.x * blockDim.x + t) >> 5;
    int nW   = (gridDim.x * blockDim.x) >> 5;
    const uint4* xf4 = reinterpret_cast<const uint4*>(g_xfh);
    float lmax = 0.0f;
    for (int e0 = wid * 2; e0 < cfg::EPT; e0 += nW * 2) {
        int e = e0 + sub;
        float ts = 0.0f;
        bool act = (e < cfg::EPT);
        if (act) {
            int r = prow[e], c = pcol[e];
            uint4 av = __ldg(&xf4[(size_t)r * 16 + sl]);
            uint4 bv = __ldg(&xf4[(size_t)c * 16 + sl]);
            ts = dot8h(av, bv);
        }
#pragma unroll
        for (int o = 8; o; o >>= 1) ts += __shfl_xor_sync(0xffffffffu, ts, o);
        if (sl == 0 && act) {
            float wv = fmaxf(ts, 0.0f);
            outw[e] = wv;
            lmax = fmaxf(lmax, wv);
        }
    }
    atomicMax(&smax, __float_as_uint(lmax));
    __syncthreads();
    if (threadIdx.x == 0) atomicMax(&g_wmax, smax);
}

// scale w in place (vectorized; w base is only 4B-aligned: 3-elem prologue,
// float4 body, scalar tail); emit ot_loss
__global__ void k_scale(float* __restrict__ out) {
    float inv = 1.0f / (__uint_as_float(g_wmax) + 1e-8f);
    float* w = out + (size_t)cfg::N * cfg::D + 1;
    constexpr size_t n4 = (size_t)(cfg::EPT - 3) / 4;
    if (blockIdx.x == 0 && threadIdx.x == 0) {
        out[(size_t)cfg::N * cfg::D] = g_loss;
        w[0] *= inv; w[1] *= inv; w[2] *= inv;
        for (size_t e = 3 + n4 * 4; e < (size_t)cfg::EPT; ++e) w[e] *= inv;
    }
    float4* w4 = reinterpret_cast<float4*>(w + 3);
    size_t idx    = (size_t)blockIdx.x * blockDim.x + threadIdx.x;
    size_t stride = (size_t)gridDim.x * blockDim.x;
    for (size_t i = idx; i < n4; i += stride) {
        float4 v = w4[i];
        v.x *= inv; v.y *= inv; v.z *= inv; v.w *= inv;
        w4[i] = v;
    }
}

// ---------------- launch ----------------
extern "C" void kernel_launch(void* const* d_in, const int* in_sizes, int n_in,
                              void* d_out, int out_size) {
    const float* x     = (const float*)d_in[0];
    const int*   ei    = (const int*)d_in[1];
    const float* ew    = (const float*)d_in[2];
    const int*   pei   = (const int*)d_in[3];
    const float* pt    = (const float*)d_in[4];
    const float* alpha = (const float*)d_in[5];
    const float* gamma = (const float*)d_in[6];
    float* out = (float*)d_out;

    const int* row  = ei;
    const int* col  = ei + cfg::E;
    const int* prow = pei;
    const int* pcol = pei + cfg::EPT;

    cudaFuncSetAttribute(k_ck, cudaFuncAttributeMaxDynamicSharedMemorySize, 98304);

    k_init<<<512, 256>>>(pt);
    k_count<<<(cfg::E + 255) / 256, 256>>>(row, col);
    k_node<<<(cfg::N + 255) / 256, 256>>>();
    k_xd<<<2048, 256>>>(x);
    k_fill<<<(cfg::E + 255) / 256, 256>>>(row, col, ew);
    k_aggr<<<(cfg::N * 32 + 255) / 256, 256>>>();
    k_ck<<<(cfg::N + 127) / 128, 256, 98304>>>(x, gamma);   // includes Ktu0

    for (int j = 1; j <= cfg::ITERS; ++j)
        k_ua<<<(cfg::N + 255) / 256, 256>>>(j);

    k_final<<<2048, 256>>>(x, pt, alpha, out);
    k_edge<<<8192, 256>>>(prow, pcol, out + (size_t)cfg::N * cfg::D + 1);
    k_scale<<<4096, 256>>>(out);
}